// round 2
// baseline (speedup 1.0000x reference)
#include <cuda_runtime.h>
#include <math.h>

#define Bn 128
#define Hn 256
#define Wn 256

// 64MB each scratch (device globals: allowed, no cudaMalloc)
__device__ float2 g_s1[Bn * Hn * Wn];   // after row FFT, layout [b][kw][h]
__device__ float2 g_s2[Bn * Hn * Wn];   // after col fwd+mask+inv, layout [b][h][kw]
__device__ float2 g_tw[256];            // w256^n forward twiddles

__global__ void k_tw() {
    int n = threadIdx.x;
    float s, c;
    sincosf(-6.283185307179586f * (float)n / 256.0f, &s, &c);
    g_tw[n] = make_float2(c, s);
}

__device__ __forceinline__ float2 cmul(float2 a, float2 b) {
    return make_float2(a.x * b.x - a.y * b.y, a.x * b.y + a.y * b.x);
}

// multiply by (c, S*s)  — twiddle with direction sign baked at compile time
template <int S>
__device__ __forceinline__ float2 twm(float2 x, float c, float s) {
    float si = (S < 0) ? -s : s;
    return make_float2(x.x * c - x.y * si, x.x * si + x.y * c);
}

// radix-4 butterfly, in-place on (a,b,c,d) = outputs X0..X3. S=-1 fwd, +1 inv.
template <int S>
__device__ __forceinline__ void dft4(float2& a, float2& b, float2& c, float2& d) {
    float2 t0 = make_float2(a.x + c.x, a.y + c.y);
    float2 t1 = make_float2(a.x - c.x, a.y - c.y);
    float2 t2 = make_float2(b.x + d.x, b.y + d.y);
    float2 t3 = make_float2(b.x - d.x, b.y - d.y);
    // S=-1: (-i)*t3 = (t3.y, -t3.x);  S=+1: (i)*t3 = (-t3.y, t3.x)
    float2 j3 = (S < 0) ? make_float2(t3.y, -t3.x) : make_float2(-t3.y, t3.x);
    a = make_float2(t0.x + t2.x, t0.y + t2.y);
    c = make_float2(t0.x - t2.x, t0.y - t2.y);
    b = make_float2(t1.x + j3.x, t1.y + j3.y);
    d = make_float2(t1.x - j3.x, t1.y - j3.y);
}

// 16-pt DFT fully in registers (4x4 CT). out[k] = sum_n in[n] * w16^(S*n*k)
template <int S>
__device__ __forceinline__ void dft16(const float2* in, float2* out) {
    float2 t[16];
    // inner DFT4 over n1 of in[4*n1+n2], twiddle w16^(n2*k1), store t[4*n2+k1]
    {   // n2 = 0: e = 0,0,0
        float2 a = in[0], b = in[4], c = in[8], d = in[12];
        dft4<S>(a, b, c, d);
        t[0] = a; t[1] = b; t[2] = c; t[3] = d;
    }
    {   // n2 = 1: e = 1,2,3
        float2 a = in[1], b = in[5], c = in[9], d = in[13];
        dft4<S>(a, b, c, d);
        t[4] = a;
        t[5] = twm<S>(b, 0.92387953251f, 0.38268343236f);
        t[6] = twm<S>(c, 0.70710678119f, 0.70710678119f);
        t[7] = twm<S>(d, 0.38268343236f, 0.92387953251f);
    }
    {   // n2 = 2: e = 2,4,6
        float2 a = in[2], b = in[6], c = in[10], d = in[14];
        dft4<S>(a, b, c, d);
        t[8]  = a;
        t[9]  = twm<S>(b, 0.70710678119f, 0.70710678119f);
        t[10] = twm<S>(c, 0.0f, 1.0f);
        t[11] = twm<S>(d, -0.70710678119f, 0.70710678119f);
    }
    {   // n2 = 3: e = 3,6,9
        float2 a = in[3], b = in[7], c = in[11], d = in[15];
        dft4<S>(a, b, c, d);
        t[12] = a;
        t[13] = twm<S>(b, 0.38268343236f, 0.92387953251f);
        t[14] = twm<S>(c, -0.70710678119f, 0.70710678119f);
        t[15] = twm<S>(d, -0.92387953251f, -0.38268343236f);
    }
    // outer DFT4 over n2 at fixed k1; out[k1 + 4*k2]
#pragma unroll
    for (int k1 = 0; k1 < 4; k1++) {
        float2 a = t[k1], b = t[4 + k1], c = t[8 + k1], d = t[12 + k1];
        dft4<S>(a, b, c, d);
        out[k1] = a; out[k1 + 4] = b; out[k1 + 8] = c; out[k1 + 12] = d;
    }
}

// 256-pt FFT by a 16-thread group. On entry thread l holds v[n1] = x[16*n1 + l].
// On exit thread l holds v[k2] = X[l + 16*k2]. w = base twiddle e^(S*2*pi*i*l/256).
// mre/mim: this group's padded transpose region (16 rows, stride 17 floats).
template <int S>
__device__ __forceinline__ void fft256_group(float2 v[16], int l, float* mre, float* mim, float2 w) {
    float2 A[16];
    dft16<S>(v, A);
    // outer twiddle w256^(l*k1), chained powers
    float2 t = w;
#pragma unroll
    for (int k1 = 1; k1 < 16; k1++) {
        A[k1] = cmul(A[k1], t);
        t = cmul(t, w);
    }
    __syncwarp();
#pragma unroll
    for (int k1 = 0; k1 < 16; k1++) {
        mre[k1 * 17 + l] = A[k1].x;
        mim[k1 * 17 + l] = A[k1].y;
    }
    __syncwarp();
    float2 Cc[16];
#pragma unroll
    for (int n2 = 0; n2 < 16; n2++) {
        Cc[n2] = make_float2(mre[l * 17 + n2], mim[l * 17 + n2]);
    }
    __syncwarp();
    dft16<S>(Cc, v);
}

// K1: forward FFT along w for 16 rows per block, transpose-store to g_s1[b][kw][h]
__global__ __launch_bounds__(256) void k_rows_fwd(const float* __restrict__ x) {
    __shared__ float pool[8704];   // re: [0,4352), im: [4352,8704)
    int tid = threadIdx.x;
    int g = tid >> 4, l = tid & 15;
    int blk = blockIdx.x;
    int b = blk >> 4;
    int h0 = (blk & 15) << 4;
    int h = h0 + g;

    const float* row = x + (((size_t)b * Hn + h) << 8);
    float2 v[16];
#pragma unroll
    for (int n1 = 0; n1 < 16; n1++)
        v[n1] = make_float2(row[(n1 << 4) + l], 0.0f);

    float2 w = g_tw[l];
    fft256_group<-1>(v, l, pool + g * 272, pool + 4352 + g * 272, w);

    __syncthreads();   // all groups done with transpose regions; reuse pool as block tile
#pragma unroll
    for (int k2 = 0; k2 < 16; k2++) {
        int wf = l + (k2 << 4);
        pool[wf * 17 + g] = v[k2].x;
        pool[4352 + wf * 17 + g] = v[k2].y;
    }
    __syncthreads();
    float2* outp = g_s1 + ((size_t)b * Hn * Wn);
    for (int i = tid; i < 4096; i += 256) {
        int wf = i >> 4, gg = i & 15;
        outp[((size_t)wf << 8) + h0 + gg] =
            make_float2(pool[wf * 17 + gg], pool[4352 + wf * 17 + gg]);
    }
}

// K2: per (b, 16 columns): fwd FFT over h, mask multiply, inverse FFT over h.
__global__ __launch_bounds__(256) void k_cols(const float* __restrict__ pi,
                                              const int* __restrict__ cid) {
    __shared__ float pool[8704];
    __shared__ unsigned char cids[4352];   // [h'][j] padded stride 17
    __shared__ float pis[64];
    int tid = threadIdx.x;
    int g = tid >> 4, l = tid & 15;
    int blk = blockIdx.x;
    int b = blk >> 4;
    int w0 = (blk & 15) << 4;
    int bp = b ^ 64;      // batch fftshift
    int wp0 = w0 ^ 128;   // w fftshift (16-aligned block, safe)

    if (tid < 64) pis[tid] = pi[bp * 64 + tid] * (1.0f / 65536.0f);  // WEIGHT_FACTOR=1, ifft norm folded
    for (int i = tid; i < 4096; i += 256) {
        int hh = i >> 4, j = i & 15;
        cids[hh * 17 + j] = (unsigned char)cid[(hh << 8) + wp0 + j];
    }
    __syncthreads();

    int kw = w0 + g;
    const float2* colp = g_s1 + (((size_t)b * Wn + kw) << 8);
    float2 v[16];
#pragma unroll
    for (int n1 = 0; n1 < 16; n1++)
        v[n1] = colp[(n1 << 4) + l];

    float* mre = pool + g * 272;
    float* mim = pool + 4352 + g * 272;
    float2 wf = g_tw[l];
    fft256_group<-1>(v, l, mre, mim, wf);

    // mask: thread l holds kh = l + 16*k2
#pragma unroll
    for (int k2 = 0; k2 < 16; k2++) {
        int khs = (l + (k2 << 4)) ^ 128;
        unsigned int cv = cids[khs * 17 + g];
        float s = (cv < 64u) ? pis[cv] : (1.0f / 65536.0f);
        v[k2].x *= s;
        v[k2].y *= s;
    }

    // forward output distribution == inverse input distribution: no exchange needed
    float2 wi = make_float2(wf.x, -wf.y);
    fft256_group<1>(v, l, mre, mim, wi);

    __syncthreads();
#pragma unroll
    for (int k2 = 0; k2 < 16; k2++) {
        int hh = l + (k2 << 4);
        pool[hh * 17 + g] = v[k2].x;
        pool[4352 + hh * 17 + g] = v[k2].y;
    }
    __syncthreads();
    float2* outp = g_s2 + ((size_t)b * Hn * Wn);
    for (int i = tid; i < 4096; i += 256) {
        int hh = i >> 4, j = i & 15;
        outp[((size_t)hh << 8) + w0 + j] =
            make_float2(pool[hh * 17 + j], pool[4352 + hh * 17 + j]);
    }
}

// K3: inverse FFT along w, abs, write 3 output channels.
__global__ __launch_bounds__(256) void k_rows_inv(const float* __restrict__ x,
                                                  float* __restrict__ out) {
    __shared__ float pool[8704];
    int tid = threadIdx.x;
    int g = tid >> 4, l = tid & 15;
    int blk = blockIdx.x;
    int b = blk >> 4;
    int h0 = (blk & 15) << 4;
    int h = h0 + g;

    const float2* rowp = g_s2 + (((size_t)b * Hn + h) << 8);
    float2 v[16];
#pragma unroll
    for (int n1 = 0; n1 < 16; n1++)
        v[n1] = rowp[(n1 << 4) + l];

    float2 wt = g_tw[l];
    float2 wi = make_float2(wt.x, -wt.y);
    fft256_group<1>(v, l, pool + g * 272, pool + 4352 + g * 272, wi);

    const float* xrow = x + (((size_t)b * Hn + h) << 8);
    float* o0 = out + ((((size_t)b * 3 + 0) * Hn + h) << 8);
    float* o1 = out + ((((size_t)b * 3 + 1) * Hn + h) << 8);
    float* o2 = out + ((((size_t)b * 3 + 2) * Hn + h) << 8);
#pragma unroll
    for (int k2 = 0; k2 < 16; k2++) {
        int wp = l + (k2 << 4);
        float xv = xrow[wp];
        float mg = sqrtf(v[k2].x * v[k2].x + v[k2].y * v[k2].y);
        o0[wp] = xv;
        o1[wp] = mg;
        o2[wp] = fabsf(mg - xv);
    }
}

__global__ void k_pi_copy(const float* __restrict__ pi, float* __restrict__ out, int n) {
    int i = blockIdx.x * 256 + threadIdx.x;
    if (i < n) out[(size_t)25165824 + i] = pi[i];
}

extern "C" void kernel_launch(void* const* d_in, const int* in_sizes, int n_in,
                              void* d_out, int out_size) {
    const float* x   = (const float*)d_in[0];
    const float* pi  = (const float*)d_in[1];
    const int*   cid = (const int*)d_in[2];
    float* out = (float*)d_out;

    k_tw<<<1, 256>>>();
    k_rows_fwd<<<2048, 256>>>(x);
    k_cols<<<2048, 256>>>(pi, cid);
    k_rows_inv<<<2048, 256>>>(x, out);

    int tail = out_size - 25165824;   // pattern_importance pass-through, if packed
    if (tail > 0) {
        int nblk = (tail + 255) / 256;
        k_pi_copy<<<nblk, 256>>>(pi, out, tail);
    }
}

// round 4
// speedup vs baseline: 1.5927x; 1.5927x over previous
#include <cuda_runtime.h>
#include <cuda_fp16.h>
#include <math.h>

#define Bn 128
#define Hn 256
#define Wn 256

// fp16 complex scratch (device globals: allowed, no cudaMalloc). 33.5MB each.
__device__ __half2 g_s1h[Bn * Hn * Wn];   // after row FFT, layout [b][kw][h]
__device__ __half2 g_s2h[Bn * Hn * Wn];   // after col fwd+mask+inv, layout [b][h][kw]
__device__ unsigned char g_cid8[Hn * Wn]; // cluster ids packed to u8

__device__ __forceinline__ float2 cmul(float2 a, float2 b) {
    return make_float2(a.x * b.x - a.y * b.y, a.x * b.y + a.y * b.x);
}

template <int S>
__device__ __forceinline__ float2 twm(float2 x, float c, float s) {
    float si = (S < 0) ? -s : s;
    return make_float2(x.x * c - x.y * si, x.x * si + x.y * c);
}

// radix-4 butterfly, in-place. S=-1 fwd, +1 inv.
template <int S>
__device__ __forceinline__ void dft4(float2& a, float2& b, float2& c, float2& d) {
    float2 t0 = make_float2(a.x + c.x, a.y + c.y);
    float2 t1 = make_float2(a.x - c.x, a.y - c.y);
    float2 t2 = make_float2(b.x + d.x, b.y + d.y);
    float2 t3 = make_float2(b.x - d.x, b.y - d.y);
    float2 j3 = (S < 0) ? make_float2(t3.y, -t3.x) : make_float2(-t3.y, t3.x);
    a = make_float2(t0.x + t2.x, t0.y + t2.y);
    c = make_float2(t0.x - t2.x, t0.y - t2.y);
    b = make_float2(t1.x + j3.x, t1.y + j3.y);
    d = make_float2(t1.x - j3.x, t1.y - j3.y);
}

// 16-pt DFT in registers (4x4 CT).
template <int S>
__device__ __forceinline__ void dft16(const float2* in, float2* out) {
    float2 t[16];
    {
        float2 a = in[0], b = in[4], c = in[8], d = in[12];
        dft4<S>(a, b, c, d);
        t[0] = a; t[1] = b; t[2] = c; t[3] = d;
    }
    {
        float2 a = in[1], b = in[5], c = in[9], d = in[13];
        dft4<S>(a, b, c, d);
        t[4] = a;
        t[5] = twm<S>(b, 0.92387953251f, 0.38268343236f);
        t[6] = twm<S>(c, 0.70710678119f, 0.70710678119f);
        t[7] = twm<S>(d, 0.38268343236f, 0.92387953251f);
    }
    {
        float2 a = in[2], b = in[6], c = in[10], d = in[14];
        dft4<S>(a, b, c, d);
        t[8]  = a;
        t[9]  = twm<S>(b, 0.70710678119f, 0.70710678119f);
        t[10] = twm<S>(c, 0.0f, 1.0f);
        t[11] = twm<S>(d, -0.70710678119f, 0.70710678119f);
    }
    {
        float2 a = in[3], b = in[7], c = in[11], d = in[15];
        dft4<S>(a, b, c, d);
        t[12] = a;
        t[13] = twm<S>(b, 0.38268343236f, 0.92387953251f);
        t[14] = twm<S>(c, -0.70710678119f, 0.70710678119f);
        t[15] = twm<S>(d, -0.92387953251f, -0.38268343236f);
    }
#pragma unroll
    for (int k1 = 0; k1 < 4; k1++) {
        float2 a = t[k1], b = t[4 + k1], c = t[8 + k1], d = t[12 + k1];
        dft4<S>(a, b, c, d);
        out[k1] = a; out[k1 + 4] = b; out[k1 + 8] = c; out[k1 + 12] = d;
    }
}

// 256-pt FFT by a 16-thread group. Entry: thread l holds v[n1]=x[16*n1+l].
// Exit: thread l holds v[k2]=X[l+16*k2]. m: this group's float2 region (16 rows, stride 17).
// w = e^(S*2*pi*i*l/256).
template <int S>
__device__ __forceinline__ void fft256_group(float2 v[16], int l, float2* m, float2 w) {
    float2 A[16];
    dft16<S>(v, A);
    float2 t = w;
#pragma unroll
    for (int k1 = 1; k1 < 16; k1++) {
        A[k1] = cmul(A[k1], t);
        t = cmul(t, w);
    }
    __syncwarp();
#pragma unroll
    for (int k1 = 0; k1 < 16; k1++)
        m[k1 * 17 + l] = A[k1];
    __syncwarp();
    float2 Cc[16];
#pragma unroll
    for (int n2 = 0; n2 < 16; n2++)
        Cc[n2] = m[l * 17 + n2];
    __syncwarp();
    dft16<S>(Cc, v);
}

__device__ __forceinline__ float2 base_tw(int l) {
    float s, c;
    sincosf(-6.283185307179586f * (float)l * (1.0f / 256.0f), &s, &c);
    return make_float2(c, s);
}

// K1: fwd FFT along w for 16 rows/block, transpose-store g_s1h[b][kw][h] (fp16).
// Also writes the x pass-through channel and packs cid -> u8.
__global__ __launch_bounds__(256) void k_rows_fwd(const float* __restrict__ x,
                                                  const int* __restrict__ cid,
                                                  float* __restrict__ out) {
    __shared__ float2 pool[4352];   // 16 groups * 272, then reused as 256x17 tile
    int tid = threadIdx.x;
    int g = tid >> 4, l = tid & 15;
    int blk = blockIdx.x;
    int b = blk >> 4;
    int h0 = (blk & 15) << 4;
    int h = h0 + g;

    if (blk < 16) {   // pack cid to u8 (done by b=0 blocks; K2 runs after K1 completes)
        for (int i = tid; i < 4096; i += 256)
            g_cid8[blk * 4096 + i] = (unsigned char)cid[blk * 4096 + i];
    }

    const float* row = x + (((size_t)b * Hn + h) << 8);
    float* o0 = out + ((((size_t)b * 3 + 0) * Hn + h) << 8);
    float2 v[16];
#pragma unroll
    for (int n1 = 0; n1 < 16; n1++) {
        float xv = row[(n1 << 4) + l];
        v[n1] = make_float2(xv, 0.0f);
        o0[(n1 << 4) + l] = xv;   // pass-through channel
    }

    fft256_group<-1>(v, l, pool + g * 272, base_tw(l));

    __syncthreads();
#pragma unroll
    for (int k2 = 0; k2 < 16; k2++) {
        int wf = l + (k2 << 4);
        pool[wf * 17 + g] = v[k2];
    }
    __syncthreads();
    __half2* outp = g_s1h + ((size_t)b * Hn * Wn);
    for (int i = tid; i < 4096; i += 256) {
        int wf = i >> 4, gg = i & 15;
        outp[((size_t)wf << 8) + h0 + gg] = __float22half2_rn(pool[wf * 17 + gg]);
    }
}

// K2: per (b, 16 cols): fwd FFT over h, mask, inverse FFT over h. fp16 in/out.
__global__ __launch_bounds__(256) void k_cols(const float* __restrict__ pi) {
    __shared__ float2 pool[4352];
    __shared__ unsigned char cids[4352];   // [h][j] stride 17
    __shared__ float pis[64];
    int tid = threadIdx.x;
    int g = tid >> 4, l = tid & 15;
    int blk = blockIdx.x;
    int b = blk >> 4;
    int w0 = (blk & 15) << 4;
    int bp = b ^ 64;      // batch fftshift
    int wp0 = w0 ^ 128;   // w fftshift

    if (tid < 64) pis[tid] = pi[bp * 64 + tid] * (1.0f / 65536.0f);
    for (int i = tid; i < 4096; i += 256) {
        int hh = i >> 4, j = i & 15;
        cids[hh * 17 + j] = g_cid8[(hh << 8) + wp0 + j];
    }
    __syncthreads();

    int kw = w0 + g;
    const __half2* colp = g_s1h + (((size_t)b * Wn + kw) << 8);
    float2 v[16];
#pragma unroll
    for (int n1 = 0; n1 < 16; n1++)
        v[n1] = __half22float2(colp[(n1 << 4) + l]);

    float2* m = pool + g * 272;
    float2 wf = base_tw(l);
    fft256_group<-1>(v, l, m, wf);

#pragma unroll
    for (int k2 = 0; k2 < 16; k2++) {
        int khs = (l + (k2 << 4)) ^ 128;
        unsigned int cv = cids[khs * 17 + g];
        float s = (cv < 64u) ? pis[cv] : (1.0f / 65536.0f);
        v[k2].x *= s;
        v[k2].y *= s;
    }

    // fwd output distribution == inverse input distribution: no exchange needed
    float2 wi = make_float2(wf.x, -wf.y);
    fft256_group<1>(v, l, m, wi);

    __syncthreads();
#pragma unroll
    for (int k2 = 0; k2 < 16; k2++) {
        int hh = l + (k2 << 4);
        pool[hh * 17 + g] = v[k2];
    }
    __syncthreads();
    __half2* outp = g_s2h + ((size_t)b * Hn * Wn);
    for (int i = tid; i < 4096; i += 256) {
        int hh = i >> 4, j = i & 15;
        outp[((size_t)hh << 8) + w0 + j] = __float22half2_rn(pool[hh * 17 + j]);
    }
}

// K3: inverse FFT along w, abs, write channels 1 and 2.
__global__ __launch_bounds__(256) void k_rows_inv(const float* __restrict__ x,
                                                  float* __restrict__ out) {
    __shared__ float2 pool[4352];
    int tid = threadIdx.x;
    int g = tid >> 4, l = tid & 15;
    int blk = blockIdx.x;
    int b = blk >> 4;
    int h0 = (blk & 15) << 4;
    int h = h0 + g;

    const __half2* rowp = g_s2h + (((size_t)b * Hn + h) << 8);
    float2 v[16];
#pragma unroll
    for (int n1 = 0; n1 < 16; n1++)
        v[n1] = __half22float2(rowp[(n1 << 4) + l]);

    float2 wt = base_tw(l);
    float2 wi = make_float2(wt.x, -wt.y);
    fft256_group<1>(v, l, pool + g * 272, wi);

    const float* xrow = x + (((size_t)b * Hn + h) << 8);
    float* o1 = out + ((((size_t)b * 3 + 1) * Hn + h) << 8);
    float* o2 = out + ((((size_t)b * 3 + 2) * Hn + h) << 8);
#pragma unroll
    for (int k2 = 0; k2 < 16; k2++) {
        int wp = l + (k2 << 4);
        float xv = xrow[wp];
        float mg = sqrtf(v[k2].x * v[k2].x + v[k2].y * v[k2].y);
        o1[wp] = mg;
        o2[wp] = fabsf(mg - xv);
    }
}

__global__ void k_pi_copy(const float* __restrict__ pi, float* __restrict__ out, int n) {
    int i = blockIdx.x * 256 + threadIdx.x;
    if (i < n) out[(size_t)25165824 + i] = pi[i];
}

extern "C" void kernel_launch(void* const* d_in, const int* in_sizes, int n_in,
                              void* d_out, int out_size) {
    const float* x   = (const float*)d_in[0];
    const float* pi  = (const float*)d_in[1];
    const int*   cid = (const int*)d_in[2];
    float* out = (float*)d_out;

    k_rows_fwd<<<2048, 256>>>(x, cid, out);
    k_cols<<<2048, 256>>>(pi);
    k_rows_inv<<<2048, 256>>>(x, out);

    int tail = out_size - 25165824;   // pattern_importance pass-through
    if (tail > 0) {
        int nblk = (tail + 255) / 256;
        k_pi_copy<<<nblk, 256>>>(pi, out, tail);
    }
}